// round 1
// baseline (speedup 1.0000x reference)
#include <cuda_runtime.h>
#include <cuda_bf16.h>
#include <cstdint>

// Problem constants
#define BB   64      // batch
#define TT   512     // time steps
#define DD   128     // input dim
#define HH   256     // hidden dim
#define G4H  1024    // 4*H

// ---------------------------------------------------------------------------
// Device scratch (allocation-free rule: __device__ globals)
// ---------------------------------------------------------------------------
__device__ float g_Gv[(size_t)BB * TT * G4H];   // 128MB  gate pre-act val
__device__ float g_Gl[(size_t)BB * TT * G4H];   // 128MB  gate pre-act lb
__device__ float g_Gu[(size_t)BB * TT * G4H];   // 128MB  gate pre-act ub
__device__ float g_H[2 * 3 * BB * HH];          // ping-pong h state [pp][var][B*H]
__device__ unsigned int g_bar_cnt;              // grid barrier counter

// ---------------------------------------------------------------------------
// Helpers
// ---------------------------------------------------------------------------
__device__ __forceinline__ float sigf(float x) {
    return __fdividef(1.0f, 1.0f + __expf(-x));
}
__device__ __forceinline__ float tanhf_(float x) {
    return __fdividef(2.0f, 1.0f + __expf(-2.0f * x)) - 1.0f;
}
__device__ __forceinline__ float min4f(float a, float b, float c, float d) {
    return fminf(fminf(a, b), fminf(c, d));
}
__device__ __forceinline__ float max4f(float a, float b, float c, float d) {
    return fmaxf(fmaxf(a, b), fmaxf(c, d));
}

// ---------------------------------------------------------------------------
// Kernel 0: reset grid-barrier counter (each launch / replay)
// ---------------------------------------------------------------------------
__global__ void bar_reset_kernel() { g_bar_cnt = 0u; }

// ---------------------------------------------------------------------------
// Kernel 1: gx = interval-linear(x, W_ih) + b   -> g_Gv/g_Gl/g_Gu
// Tiled GEMM: M = B*T = 32768, N = 1024, K = 128. CTA tile 64x64, 256 thr, 4x4 micro.
// Three accumulators per output: val (xv*W), mu ((lb+ub)/2 * W), r ((ub-lb)/2 * |W|).
// ---------------------------------------------------------------------------
#define GM 64
#define GN 64
#define GK 16

__global__ __launch_bounds__(256) void gx_gemm_kernel(
    const float* __restrict__ xv, const float* __restrict__ xl,
    const float* __restrict__ xu, const float* __restrict__ W,
    const float* __restrict__ bias)
{
    __shared__ float sAv[GK][GM + 4];
    __shared__ float sAm[GK][GM + 4];
    __shared__ float sAr[GK][GM + 4];
    __shared__ float sB [GK][GN + 4];

    const int n0 = blockIdx.x * GN;
    const int m0 = blockIdx.y * GM;
    const int tid = threadIdx.x;
    const int tx = tid & 15;        // 0..15 -> n micro
    const int ty = tid >> 4;        // 0..15 -> m micro

    float av[4][4], am[4][4], ar[4][4];
#pragma unroll
    for (int i = 0; i < 4; i++)
#pragma unroll
        for (int j = 0; j < 4; j++) { av[i][j] = 0.f; am[i][j] = 0.f; ar[i][j] = 0.f; }

    const int ml = tid >> 2;        // 0..63 row for staging
    const int kq = tid & 3;         // 0..3  float4 slot along k

    for (int k0 = 0; k0 < DD; k0 += GK) {
        // --- stage A (x val / mu / r), transposed to [k][m] ---
        {
            const float4 v4 = *(const float4*)(xv + (size_t)(m0 + ml) * DD + k0 + kq * 4);
            const float4 l4 = *(const float4*)(xl + (size_t)(m0 + ml) * DD + k0 + kq * 4);
            const float4 u4 = *(const float4*)(xu + (size_t)(m0 + ml) * DD + k0 + kq * 4);
            const float vv[4] = {v4.x, v4.y, v4.z, v4.w};
            const float ll[4] = {l4.x, l4.y, l4.z, l4.w};
            const float uu[4] = {u4.x, u4.y, u4.z, u4.w};
#pragma unroll
            for (int j = 0; j < 4; j++) {
                int k = kq * 4 + j;
                sAv[k][ml] = vv[j];
                sAm[k][ml] = 0.5f * (ll[j] + uu[j]);
                sAr[k][ml] = 0.5f * (uu[j] - ll[j]);
            }
        }
        // --- stage B (W_ih), transposed to [k][n] ---
        {
            const float4 w4 = *(const float4*)(W + (size_t)(n0 + ml) * DD + k0 + kq * 4);
            const float ww[4] = {w4.x, w4.y, w4.z, w4.w};
#pragma unroll
            for (int j = 0; j < 4; j++) sB[kq * 4 + j][ml] = ww[j];
        }
        __syncthreads();

#pragma unroll
        for (int k = 0; k < GK; k++) {
            const float4 b4 = *(const float4*)&sB[k][tx * 4];
            const float rb[4]  = {b4.x, b4.y, b4.z, b4.w};
            const float rba[4] = {fabsf(b4.x), fabsf(b4.y), fabsf(b4.z), fabsf(b4.w)};
            const float4 v4 = *(const float4*)&sAv[k][ty * 4];
            const float4 m4 = *(const float4*)&sAm[k][ty * 4];
            const float4 r4 = *(const float4*)&sAr[k][ty * 4];
            const float rav[4] = {v4.x, v4.y, v4.z, v4.w};
            const float ram[4] = {m4.x, m4.y, m4.z, m4.w};
            const float rar[4] = {r4.x, r4.y, r4.z, r4.w};
#pragma unroll
            for (int i = 0; i < 4; i++)
#pragma unroll
                for (int j = 0; j < 4; j++) {
                    av[i][j] = fmaf(rav[i], rb[j],  av[i][j]);
                    am[i][j] = fmaf(ram[i], rb[j],  am[i][j]);
                    ar[i][j] = fmaf(rar[i], rba[j], ar[i][j]);
                }
        }
        __syncthreads();
    }

    // epilogue: add bias, write val / (mu - r) / (mu + r)
    float bb4[4];
#pragma unroll
    for (int j = 0; j < 4; j++) bb4[j] = bias[n0 + tx * 4 + j];
#pragma unroll
    for (int i = 0; i < 4; i++) {
        const int m = m0 + ty * 4 + i;
#pragma unroll
        for (int j = 0; j < 4; j++) {
            const int n = n0 + tx * 4 + j;
            const size_t o = (size_t)m * G4H + n;
            const float v  = av[i][j] + bb4[j];
            const float mu = am[i][j] + bb4[j];
            const float r  = ar[i][j];
            g_Gv[o] = v;
            g_Gl[o] = mu - r;
            g_Gu[o] = mu + r;
        }
    }
}

// ---------------------------------------------------------------------------
// Kernel 2: persistent recurrent scan.
// Grid: 128 CTAs x 128 threads (1 CTA/SM, co-resident -> software grid barrier OK).
// CTA covers 16 batch rows x 8 h columns. Thread owns one (b,h) cell:
//   - c state (val/lb/ub) in registers for all 512 steps
//   - per step: 12 dot products over k=0..255 (4 gates x {val, mu, r})
// W_hh tile (+ |W|) staged to smem ONCE.  h state ping-pongs via global (L2),
// read with __ldcg / written with __stcg (L1 incoherent across SMs).
// ---------------------------------------------------------------------------
#define NCTA 128
#define NTHR 128

__device__ __forceinline__ void grid_barrier(unsigned int target) {
    __threadfence();
    __syncthreads();
    if (threadIdx.x == 0) {
        atomicAdd(&g_bar_cnt, 1u);
        while (*(volatile unsigned int*)&g_bar_cnt < target) { }
    }
    __syncthreads();
    __threadfence();
}

__global__ __launch_bounds__(NTHR, 1) void scan_kernel(
    const float* __restrict__ Whh, const float* __restrict__ h0,
    const float* __restrict__ c0, float* __restrict__ out)
{
    extern __shared__ float smem[];
    float* sW  = smem;               // [256][8][4] = 8192 floats
    float* sWa = smem + 8192;        // |W| copy    = 8192 floats
    float* shv = smem + 16384;       // [16][256]
    float* shm = smem + 20480;
    float* shr = smem + 24576;       // total 28672 floats = 112KB

    const int tid = threadIdx.x;
    const int bc = blockIdx.x & 3;          // batch chunk (0..3)
    const int hc = blockIdx.x >> 2;         // h chunk (0..31)
    const int b_base = bc * 16;
    const int h_base = hc * 8;
    const int bL = tid >> 3;                // 0..15 local batch
    const int hL = tid & 7;                 // 0..7  local h
    const int b = b_base + bL;
    const int h = h_base + hL;

    // --- stage W tile once: sW[k*32 + hh*4 + g] = Whh[(g*256 + h_base+hh)*256 + k]
    for (int idx = tid; idx < 8192; idx += NTHR) {
        const int g  = idx & 3;
        const int hh = (idx >> 2) & 7;
        const int k  = idx >> 5;
        const float w = Whh[(size_t)(g * HH + h_base + hh) * HH + k];
        sW[idx]  = w;
        sWa[idx] = fabsf(w);
    }

    // --- c state in registers
    float cv = c0[b * HH + h];
    float cl = cv, cu = cv;

    const float4* wP  = (const float4*)sW  + hL;   // stride 8 float4 per k
    const float4* wAP = (const float4*)sWa + hL;

    for (int t = 0; t < TT; t++) {
        if (t > 0) grid_barrier((unsigned)t * NCTA);

        // --- stage h(prev) rows for this CTA's 16 batches ---
        if (t == 0) {
            for (int idx = tid; idx < 16 * HH; idx += NTHR) {
                const float v = h0[b_base * HH + idx];
                shv[idx] = v; shm[idx] = v; shr[idx] = 0.f;
            }
        } else {
            const float* Hs = g_H + ((t - 1) & 1) * (3 * BB * HH);
            const int base = b_base * HH;
            for (int idx = tid; idx < 16 * HH; idx += NTHR) {
                const float v = __ldcg(Hs + base + idx);
                const float l = __ldcg(Hs + BB * HH + base + idx);
                const float u = __ldcg(Hs + 2 * BB * HH + base + idx);
                shv[idx] = v;
                shm[idx] = 0.5f * (l + u);
                shr[idx] = 0.5f * (u - l);
            }
        }

        // --- prefetch gx (12 scalars) ---
        const int gidx = ((b << 9) + t) << 10;   // (b*512 + t) * 1024
        const float gv0 = g_Gv[gidx + h],       gl0 = g_Gl[gidx + h],       gu0 = g_Gu[gidx + h];
        const float gv1 = g_Gv[gidx + 256 + h], gl1 = g_Gl[gidx + 256 + h], gu1 = g_Gu[gidx + 256 + h];
        const float gv2 = g_Gv[gidx + 512 + h], gl2 = g_Gl[gidx + 512 + h], gu2 = g_Gu[gidx + 512 + h];
        const float gv3 = g_Gv[gidx + 768 + h], gl3 = g_Gl[gidx + 768 + h], gu3 = g_Gu[gidx + 768 + h];

        __syncthreads();

        // --- 12 dot products over k ---
        float a_v0 = 0.f, a_v1 = 0.f, a_v2 = 0.f, a_v3 = 0.f;
        float a_m0 = 0.f, a_m1 = 0.f, a_m2 = 0.f, a_m3 = 0.f;
        float a_r0 = 0.f, a_r1 = 0.f, a_r2 = 0.f, a_r3 = 0.f;
        const float* hvS = shv + (bL << 8);
        const float* hmS = shm + (bL << 8);
        const float* hrS = shr + (bL << 8);
#pragma unroll 8
        for (int k = 0; k < HH; k++) {
            const float4 w  = wP [k * 8];
            const float4 wa = wAP[k * 8];
            const float hv_ = hvS[k];
            const float hm_ = hmS[k];
            const float hr_ = hrS[k];
            a_v0 = fmaf(hv_, w.x,  a_v0); a_v1 = fmaf(hv_, w.y,  a_v1);
            a_v2 = fmaf(hv_, w.z,  a_v2); a_v3 = fmaf(hv_, w.w,  a_v3);
            a_m0 = fmaf(hm_, w.x,  a_m0); a_m1 = fmaf(hm_, w.y,  a_m1);
            a_m2 = fmaf(hm_, w.z,  a_m2); a_m3 = fmaf(hm_, w.w,  a_m3);
            a_r0 = fmaf(hr_, wa.x, a_r0); a_r1 = fmaf(hr_, wa.y, a_r1);
            a_r2 = fmaf(hr_, wa.z, a_r2); a_r3 = fmaf(hr_, wa.w, a_r3);
        }

        // --- gate pre-activations (val/lb/ub) ---
        const float pv0 = gv0 + a_v0, pl0 = gl0 + a_m0 - a_r0, pu0 = gu0 + a_m0 + a_r0;
        const float pv1 = gv1 + a_v1, pl1 = gl1 + a_m1 - a_r1, pu1 = gu1 + a_m1 + a_r1;
        const float pv2 = gv2 + a_v2, pl2 = gl2 + a_m2 - a_r2, pu2 = gu2 + a_m2 + a_r2;
        const float pv3 = gv3 + a_v3, pl3 = gl3 + a_m3 - a_r3, pu3 = gu3 + a_m3 + a_r3;

        const float iv = sigf(pv0), il = sigf(pl0), iu = sigf(pu0);
        const float fv = sigf(pv1), fl = sigf(pl1), fu = sigf(pu1);
        const float gv = tanhf_(pv2), gl = tanhf_(pl2), gu = tanhf_(pu2);
        const float ov = sigf(pv3), ol = sigf(pl3), ou = sigf(pu3);

        // c_new = f*c + i*g   (interval products)
        const float t1 = fl * cl, t2 = fl * cu, t3 = fu * cl, t4 = fu * cu;
        const float fc_l = min4f(t1, t2, t3, t4);
        const float fc_u = max4f(t1, t2, t3, t4);
        const float fc_v = fv * cv;
        const float s1 = il * gl, s2 = il * gu, s3 = iu * gl, s4 = iu * gu;
        const float ig_l = min4f(s1, s2, s3, s4);
        const float ig_u = max4f(s1, s2, s3, s4);
        const float ig_v = iv * gv;
        cv = fc_v + ig_v;
        cl = fc_l + ig_l;
        cu = fc_u + ig_u;

        // h_new = o * tanh(c_new)
        const float tv = tanhf_(cv), tl = tanhf_(cl), tu = tanhf_(cu);
        const float u1 = ol * tl, u2 = ol * tu, u3 = ou * tl, u4 = ou * tu;
        const float hn_l = min4f(u1, u2, u3, u4);
        const float hn_u = max4f(u1, u2, u3, u4);
        const float hn_v = ov * tv;

        // --- write h state (ping-pong, L2-coherent) + output ---
        float* Hd = g_H + (t & 1) * (3 * BB * HH);
        const int hoff = b * HH + h;
        __stcg(Hd + hoff, hn_v);
        __stcg(Hd + BB * HH + hoff, hn_l);
        __stcg(Hd + 2 * BB * HH + hoff, hn_u);

        const size_t obase = ((size_t)(b << 9) + t) * HH + h;   // (b*T + t)*H + h
        out[obase] = hn_v;
        out[(size_t)BB * TT * HH + obase] = hn_l;
        out[2 * (size_t)BB * TT * HH + obase] = hn_u;
    }
}

// ---------------------------------------------------------------------------
// Launch
// ---------------------------------------------------------------------------
extern "C" void kernel_launch(void* const* d_in, const int* in_sizes, int n_in,
                              void* d_out, int out_size)
{
    const float* xv   = (const float*)d_in[0];
    const float* xl   = (const float*)d_in[1];
    const float* xu   = (const float*)d_in[2];
    const float* Wih  = (const float*)d_in[3];
    const float* Whh  = (const float*)d_in[4];
    const float* bias = (const float*)d_in[5];
    const float* h0   = (const float*)d_in[6];
    const float* c0   = (const float*)d_in[7];
    float* out = (float*)d_out;

    const int smem_bytes = 28672 * sizeof(float);   // 112 KB
    cudaFuncSetAttribute(scan_kernel, cudaFuncAttributeMaxDynamicSharedMemorySize, smem_bytes);

    bar_reset_kernel<<<1, 1>>>();
    gx_gemm_kernel<<<dim3(G4H / GN, (BB * TT) / GM), 256>>>(xv, xl, xu, Wih, bias);
    scan_kernel<<<NCTA, NTHR, smem_bytes>>>(Whh, h0, c0, out);
}